// round 7
// baseline (speedup 1.0000x reference)
#include <cuda_runtime.h>
#include <cuda_bf16.h>

#define FULL 0xFFFFFFFFu

// Per-gate Ry part: (cos(theta/2), sin(theta/2)) from ZYZ decomposition
__device__ float2 g_ry[32];
// Diagonal phase tables D0..D3: 4 x 256 complex (cos, sin)
__device__ float2 g_diag[4 * 256];

// Relabeled parity rows per gate (CNOTs folded; must match template R args)
__constant__ int c_rows[32] = {
    0x80,0x40,0x20,0x10,0x08,0x04,0x02,0x01,
    0x80,0xC0,0xE0,0xF0,0xF8,0xFC,0xFE,0xFF,
    0x80,0x40,0xA0,0x50,0xA8,0x54,0xAA,0x55,
    0x80,0xC0,0x60,0x30,0x98,0xCC,0x66,0x33
};

__device__ __host__ constexpr int parity5(int v) {
    v ^= v >> 4; v ^= v >> 2; v ^= v >> 1; return v & 1;
}

// ---- single fused prep kernel (1024 threads, one block) ----
__global__ void prep(const float* __restrict__ w) {
    __shared__ float s_lam[32], s_phi[32];
    int t = threadIdx.x;
    if (t < 32) {
        int base = t * 3;
        float ta = w[base]     * 0.5f;
        float tb = w[base + 1] * 0.5f;
        float tc = w[base + 2] * 0.5f;
        float sa = sinf(ta), ca = cosf(ta);
        float sb = sinf(tb), cb = cosf(tb);
        float sc = sinf(tc), cc = cosf(tc);
        float m00r = cb * ca, m00i = sb * sa;
        float m01r = -sb * ca, m01i = -cb * sa;
        float x = cc * m00r + sc * m00i;
        float y = cc * m00i - sc * m00r;
        float z = cc * m01r + sc * m01i;
        float q = cc * m01i - sc * m01r;
        float ct = sqrtf(x * x + y * y);
        float st = sqrtf(z * z + q * q);
        float a = -atan2f(y, x);
        float b = atan2f(q, -z);
        g_ry[t] = make_float2(ct, st);
        s_lam[t] = a - b;
        s_phi[t] = a + b;
    }
    __syncthreads();

    int j = t >> 8;
    int s = t & 255;
    float th = 0.f;
#pragma unroll
    for (int g = 0; g < 8; g++) {
        int gg = 8 * j + g;
        float sg = (__popc(c_rows[gg] & s) & 1) ? 1.f : -1.f;
        th += 0.5f * s_lam[gg] * sg;
    }
    if (j > 0) {
#pragma unroll
        for (int g = 0; g < 8; g++) {
            int gg = 8 * (j - 1) + g;
            float sg = (__popc(c_rows[gg] & s) & 1) ? 1.f : -1.f;
            th += 0.5f * s_phi[gg] * sg;
        }
    }
    float sn, cn;
    sincosf(th, &sn, &cn);
    g_diag[j * 256 + s] = make_float2(cn, sn);
}

// ---- Ry gate, 8-lane layout: lane bits = state bits 7..5, local k = bits 4..0
// new[s] = c*a[s] + sigma(s)*st*a[s^M], sigma = +1 if <R,s> odd else -1.
template<int M, int R, int G>
__device__ __forceinline__ void rygate(float (&ar)[32], float (&ai)[32], int lane8) {
    const float2 cs = g_ry[G];
    constexpr int ML = (M >> 5) & 7;
    constexpr int MK = M & 31;
    constexpr int RL = (R >> 5) & 7;
    constexpr int RK = R & 31;
    constexpr int HB = (MK >= 16) ? 16 : (MK >= 8) ? 8 : (MK >= 4) ? 4 : (MK >= 2) ? 2 : 1;

    int pl = __popc(lane8 & RL) & 1;
    float sA = pl ? cs.y : -cs.y;
    float cc = cs.x;

    if constexpr (ML != 0 && MK == 0) {
        // cross-lane, same local slot: lockstep shuffle reads old value, safe
#pragma unroll
        for (int k = 0; k < 32; k++) {
            float br = __shfl_xor_sync(FULL, ar[k], ML);
            float bi = __shfl_xor_sync(FULL, ai[k], ML);
            float sk = parity5(RK & k) ? -sA : sA;
            ar[k] = cc * ar[k] + sk * br;
            ai[k] = cc * ai[k] + sk * bi;
        }
    } else if constexpr (ML != 0) {
        // mixed: pair-complete — all shuffles of pair (k, k^MK) before any write
#pragma unroll
        for (int k = 0; k < 32; k++) {
            if ((k & HB) == 0) {
                const int k2 = k ^ MK;
                float pr = __shfl_xor_sync(FULL, ar[k2], ML);
                float pi = __shfl_xor_sync(FULL, ai[k2], ML);
                float qr = __shfl_xor_sync(FULL, ar[k],  ML);
                float qi = __shfl_xor_sync(FULL, ai[k],  ML);
                float s1 = parity5(RK & k)  ? -sA : sA;
                float s2 = parity5(RK & k2) ? -sA : sA;
                ar[k]  = cc * ar[k]  + s1 * pr;
                ai[k]  = cc * ai[k]  + s1 * pi;
                ar[k2] = cc * ar[k2] + s2 * qr;
                ai[k2] = cc * ai[k2] + s2 * qi;
            }
        }
    } else {
        // purely local pairs, in place
#pragma unroll
        for (int k = 0; k < 32; k++) {
            if ((k & HB) == 0) {
                const int k2 = k ^ MK;
                float s1 = parity5(RK & k)  ? -sA : sA;
                float s2 = parity5(RK & k2) ? -sA : sA;
                float tr = ar[k], ti = ai[k], ur = ar[k2], ui = ai[k2];
                ar[k]  = cc * tr + s1 * ur;
                ai[k]  = cc * ti + s1 * ui;
                ar[k2] = cc * ur + s2 * tr;
                ai[k2] = cc * ui + s2 * ti;
            }
        }
    }
}

__device__ __forceinline__ void applyD(float (&ar)[32], float (&ai)[32], int lane8, int j) {
    const float4* __restrict__ t = (const float4*)(g_diag + j * 256 + lane8 * 32);
#pragma unroll
    for (int h = 0; h < 16; h++) {
        float4 p = __ldg(&t[h]);
        int k = 2 * h;
        float n0r = p.x * ar[k]     - p.y * ai[k];
        float n0i = p.x * ai[k]     + p.y * ar[k];
        float n1r = p.z * ar[k + 1] - p.w * ai[k + 1];
        float n1i = p.z * ai[k + 1] + p.w * ar[k + 1];
        ar[k] = n0r;     ai[k] = n0i;
        ar[k + 1] = n1r; ai[k + 1] = n1i;
    }
}

__global__ void __launch_bounds__(128)
qsim(const float* __restrict__ x, float* __restrict__ out, int W) {
    int warp = (blockIdx.x * blockDim.x + threadIdx.x) >> 5;  // 0..W-1
    int lane = threadIdx.x & 31;
    if (warp >= W) return;
    int lane8 = lane & 7;     // state bits 7..5  (qubits 0..2)
    int g = lane >> 3;        // sample within warp (0..3)

    // ---- encoding: warp covers 4 samples (32 consecutive angles) ----
    float xq = x[warp * 32 + lane];   // sample g, angle lane8
    float sh, ch;
    __sincosf(0.5f * xq, &sh, &ch);

    float c[8], s[8];
#pragma unroll
    for (int q = 0; q < 8; q++) {
        c[q] = __shfl_sync(FULL, ch, (lane & 24) + q);
        s[q] = __shfl_sync(FULL, sh, (lane & 24) + q);
    }
    // lane8 bit (2-q) selects qubit q=0..2; k bit (7-q) selects q=3..7
    float lp = ((lane8 >> 2) & 1 ? s[0] : c[0]) *
               ((lane8 >> 1) & 1 ? s[1] : c[1]) *
               ((lane8)      & 1 ? s[2] : c[2]);

    // build product over qubits 3..7 (k bits 4..0), lp folded in
    float f[32];
    {
        float t2[2]  = { lp * c[3], lp * s[3] };
        float t4[4], t8[8], t16[16];
#pragma unroll
        for (int i = 0; i < 2; i++) { t4[2*i] = t2[i]*c[4]; t4[2*i+1] = t2[i]*s[4]; }
#pragma unroll
        for (int i = 0; i < 4; i++) { t8[2*i] = t4[i]*c[5]; t8[2*i+1] = t4[i]*s[5]; }
#pragma unroll
        for (int i = 0; i < 8; i++) { t16[2*i] = t8[i]*c[6]; t16[2*i+1] = t8[i]*s[6]; }
#pragma unroll
        for (int i = 0; i < 16; i++) { f[2*i] = t16[i]*c[7]; f[2*i+1] = t16[i]*s[7]; }
    }

    // fold in D0
    float ar[32], ai[32];
    {
        const float4* __restrict__ d0 = (const float4*)(g_diag + lane8 * 32);
#pragma unroll
        for (int h = 0; h < 16; h++) {
            float4 p = __ldg(&d0[h]);
            int k = 2 * h;
            ar[k]     = f[k]     * p.x;  ai[k]     = f[k]     * p.y;
            ar[k + 1] = f[k + 1] * p.z;  ai[k + 1] = f[k + 1] * p.w;
        }
    }

    // ---- RyBlock layer 1 ----
    rygate<0x80, 0x80,  0>(ar, ai, lane8);
    rygate<0x40, 0x40,  1>(ar, ai, lane8);
    rygate<0x20, 0x20,  2>(ar, ai, lane8);
    rygate<0x10, 0x10,  3>(ar, ai, lane8);
    rygate<0x08, 0x08,  4>(ar, ai, lane8);
    rygate<0x04, 0x04,  5>(ar, ai, lane8);
    rygate<0x02, 0x02,  6>(ar, ai, lane8);
    rygate<0x01, 0x01,  7>(ar, ai, lane8);
    applyD(ar, ai, lane8, 1);
    // ---- layer 2 ----
    rygate<0xC0, 0x80,  8>(ar, ai, lane8);
    rygate<0x60, 0xC0,  9>(ar, ai, lane8);
    rygate<0x30, 0xE0, 10>(ar, ai, lane8);
    rygate<0x18, 0xF0, 11>(ar, ai, lane8);
    rygate<0x0C, 0xF8, 12>(ar, ai, lane8);
    rygate<0x06, 0xFC, 13>(ar, ai, lane8);
    rygate<0x03, 0xFE, 14>(ar, ai, lane8);
    rygate<0x01, 0xFF, 15>(ar, ai, lane8);
    applyD(ar, ai, lane8, 2);
    // ---- layer 3 ----
    rygate<0xA0, 0x80, 16>(ar, ai, lane8);
    rygate<0x50, 0x40, 17>(ar, ai, lane8);
    rygate<0x28, 0xA0, 18>(ar, ai, lane8);
    rygate<0x14, 0x50, 19>(ar, ai, lane8);
    rygate<0x0A, 0xA8, 20>(ar, ai, lane8);
    rygate<0x05, 0x54, 21>(ar, ai, lane8);
    rygate<0x02, 0xAA, 22>(ar, ai, lane8);
    rygate<0x01, 0x55, 23>(ar, ai, lane8);
    applyD(ar, ai, lane8, 3);
    // ---- layer 4 (trailing diagonal dropped: |amp|^2 invariant) ----
    rygate<0xF0, 0x80, 24>(ar, ai, lane8);
    rygate<0x78, 0xC0, 25>(ar, ai, lane8);
    rygate<0x3C, 0x60, 26>(ar, ai, lane8);
    rygate<0x1E, 0x30, 27>(ar, ai, lane8);
    rygate<0x0F, 0x98, 28>(ar, ai, lane8);
    rygate<0x07, 0xCC, 29>(ar, ai, lane8);
    rygate<0x03, 0x66, 30>(ar, ai, lane8);
    rygate<0x01, 0x33, 31>(ar, ai, lane8);

    // ---- measurement: rows q0..q7 = 80,40,20,10,88,44,22,11 ----
    float P = 0.f, S16 = 0.f, S8 = 0.f, S4 = 0.f, S2 = 0.f, S17 = 0.f;
#pragma unroll
    for (int k = 0; k < 32; k++) {
        float p = ar[k] * ar[k] + ai[k] * ai[k];
        P   += p;
        S16 += (k & 16) ? -p : p;
        S8  += (k & 8)  ? -p : p;
        S4  += (k & 4)  ? -p : p;
        S2  += (k & 2)  ? -p : p;
        S17 += (((k >> 4) ^ k) & 1) ? -p : p;
    }
    float sg4 = (lane8 & 4) ? -1.f : 1.f;
    float sg2 = (lane8 & 2) ? -1.f : 1.f;
    float sg1 = (lane8 & 1) ? -1.f : 1.f;
    float z[8];
    z[0] = sg4 * P;   z[1] = sg2 * P;   z[2] = sg1 * P;   z[3] = S16;
    z[4] = sg4 * S8;  z[5] = sg2 * S4;  z[6] = sg1 * S2;  z[7] = S17;

#pragma unroll
    for (int off = 4; off >= 1; off >>= 1) {
#pragma unroll
        for (int i = 0; i < 8; i++)
            z[i] += __shfl_xor_sync(FULL, z[i], off);
    }
    if (lane8 == 0) {
        float4* o = (float4*)(out + warp * 32 + g * 8);
        o[0] = make_float4(z[0], z[1], z[2], z[3]);
        o[1] = make_float4(z[4], z[5], z[6], z[7]);
    }
}

extern "C" void kernel_launch(void* const* d_in, const int* in_sizes, int n_in,
                              void* d_out, int out_size) {
    const float* x = (const float*)d_in[0];
    const float* w = (const float*)d_in[1];
    float* out = (float*)d_out;
    int B = in_sizes[0] / 8;
    int W = B / 4;   // 4 samples per warp (8 lanes each)

    prep<<<1, 1024>>>(w);

    int threads = 128;
    long long total = (long long)W * 32;
    int blocks = (int)((total + threads - 1) / threads);
    qsim<<<blocks, threads>>>(x, out, W);
}

// round 8
// speedup vs baseline: 1.2471x; 1.2471x over previous
#include <cuda_runtime.h>
#include <cuda_bf16.h>

#define FULL 0xFFFFFFFFu
typedef unsigned long long ull;

// Per-gate Ry part: (cos(theta/2), sin(theta/2)) from ZYZ decomposition
__device__ float2 g_ry[32];
// Diagonal phase tables D0..D3: 4 x 256 complex (cos, sin)
__device__ float2 g_diag[4 * 256];

// Relabeled parity rows per gate (CNOTs folded; must match template R args)
__constant__ int c_rows[32] = {
    0x80,0x40,0x20,0x10,0x08,0x04,0x02,0x01,
    0x80,0xC0,0xE0,0xF0,0xF8,0xFC,0xFE,0xFF,
    0x80,0x40,0xA0,0x50,0xA8,0x54,0xAA,0x55,
    0x80,0xC0,0x60,0x30,0x98,0xCC,0x66,0x33
};

// ---- single fused prep kernel (1024 threads, one block) ----
__global__ void prep(const float* __restrict__ w) {
    __shared__ float s_lam[32], s_phi[32];
    int t = threadIdx.x;
    if (t < 32) {
        int base = t * 3;
        float ta = w[base]     * 0.5f;
        float tb = w[base + 1] * 0.5f;
        float tc = w[base + 2] * 0.5f;
        float sa = sinf(ta), ca = cosf(ta);
        float sb = sinf(tb), cb = cosf(tb);
        float sc = sinf(tc), cc = cosf(tc);
        float m00r = cb * ca, m00i = sb * sa;
        float m01r = -sb * ca, m01i = -cb * sa;
        float x = cc * m00r + sc * m00i;
        float y = cc * m00i - sc * m00r;
        float z = cc * m01r + sc * m01i;
        float q = cc * m01i - sc * m01r;
        float ct = sqrtf(x * x + y * y);
        float st = sqrtf(z * z + q * q);
        float a = -atan2f(y, x);
        float b = atan2f(q, -z);
        g_ry[t] = make_float2(ct, st);
        s_lam[t] = a - b;
        s_phi[t] = a + b;
    }
    __syncthreads();

    int j = t >> 8;
    int s = t & 255;
    float th = 0.f;
#pragma unroll
    for (int g = 0; g < 8; g++) {
        int gg = 8 * j + g;
        float sg = (__popc(c_rows[gg] & s) & 1) ? 1.f : -1.f;
        th += 0.5f * s_lam[gg] * sg;
    }
    if (j > 0) {
#pragma unroll
        for (int g = 0; g < 8; g++) {
            int gg = 8 * (j - 1) + g;
            float sg = (__popc(c_rows[gg] & s) & 1) ? 1.f : -1.f;
            th += 0.5f * s_phi[gg] * sg;
        }
    }
    float sn, cn;
    __sincosf(th, &sn, &cn);   // |err| ~4e-7, well inside 1e-3 budget
    g_diag[j * 256 + s] = make_float2(cn, sn);
}

// ---- packed fp32x2 helpers: lanes = (sample0, sample1) ----
__device__ __forceinline__ ull fma2(ull a, ull b, ull c) {
    ull d; asm("fma.rn.f32x2 %0, %1, %2, %3;" : "=l"(d) : "l"(a), "l"(b), "l"(c));
    return d;
}
__device__ __forceinline__ ull mul2(ull a, ull b) {
    ull d; asm("mul.rn.f32x2 %0, %1, %2;" : "=l"(d) : "l"(a), "l"(b));
    return d;
}
__device__ __forceinline__ ull pack2(float lo, float hi) {
    ull d; asm("mov.b64 %0, {%1, %2};" : "=l"(d) : "f"(lo), "f"(hi));
    return d;
}
__device__ __forceinline__ float lo32(ull v) { return __uint_as_float((unsigned)v); }
__device__ __forceinline__ float hi32(ull v) { return __uint_as_float((unsigned)(v >> 32)); }

// ---- Ry gate on packed 2-sample state, hazard-free, R6 ordering ----
// new[s] = c*a[s] + sigma(s)*st*a[s^M], sigma = +1 if <R,s> odd else -1.
// Coefficients identical for both packed samples.
template<int M, int R, int G>
__device__ __forceinline__ void rygate2(ull (&vr)[8], ull (&vi)[8], int lane) {
    const float2 cs = g_ry[G];
    constexpr int ML = (M >> 3) & 31;
    constexpr int MK = M & 7;
    constexpr int RL = (R >> 3) & 31;
    constexpr int RK = R & 7;
    constexpr int HB = (MK >= 4) ? 4 : ((MK >= 2) ? 2 : 1);

    int pl = __popc(lane & RL) & 1;
    float sA = pl ? cs.y : -cs.y;
    ull cc2 = pack2(cs.x, cs.x);
    ull sP  = pack2(sA, sA);
    ull sN  = pack2(-sA, -sA);

    if constexpr (ML != 0 && MK == 0) {
        // cross-lane, same local slot: lockstep shuffle reads old value, safe
#pragma unroll
        for (int k = 0; k < 8; k++) {
            ull br = __shfl_xor_sync(FULL, vr[k], ML);
            ull bi = __shfl_xor_sync(FULL, vi[k], ML);
            const bool odd = ((0x96 >> (RK & k)) & 1) != 0;
            ull sk = odd ? sN : sP;
            vr[k] = fma2(sk, br, mul2(cc2, vr[k]));
            vi[k] = fma2(sk, bi, mul2(cc2, vi[k]));
        }
    } else if constexpr (ML != 0) {
        // mixed: pair-complete — all shuffles of pair (k, k^MK) before any write
#pragma unroll
        for (int k = 0; k < 8; k++) {
            if ((k & HB) == 0) {
                const int k2 = k ^ MK;
                ull pr = __shfl_xor_sync(FULL, vr[k2], ML);
                ull pi = __shfl_xor_sync(FULL, vi[k2], ML);
                ull qr = __shfl_xor_sync(FULL, vr[k],  ML);
                ull qi = __shfl_xor_sync(FULL, vi[k],  ML);
                const bool o1 = ((0x96 >> (RK & k )) & 1) != 0;
                const bool o2 = ((0x96 >> (RK & k2)) & 1) != 0;
                ull s1 = o1 ? sN : sP;
                ull s2 = o2 ? sN : sP;
                vr[k]  = fma2(s1, pr, mul2(cc2, vr[k]));
                vi[k]  = fma2(s1, pi, mul2(cc2, vi[k]));
                vr[k2] = fma2(s2, qr, mul2(cc2, vr[k2]));
                vi[k2] = fma2(s2, qi, mul2(cc2, vi[k2]));
            }
        }
    } else {
        // purely local pairs, in place
#pragma unroll
        for (int k = 0; k < 8; k++) {
            if ((k & HB) == 0) {
                const int k2 = k ^ MK;
                const bool o1 = ((0x96 >> (RK & k )) & 1) != 0;
                const bool o2 = ((0x96 >> (RK & k2)) & 1) != 0;
                ull s1 = o1 ? sN : sP;
                ull s2 = o2 ? sN : sP;
                ull tr = vr[k], ti = vi[k], ur = vr[k2], ui = vi[k2];
                vr[k]  = fma2(s1, ur, mul2(cc2, tr));
                vi[k]  = fma2(s1, ui, mul2(cc2, ti));
                vr[k2] = fma2(s2, tr, mul2(cc2, ur));
                vi[k2] = fma2(s2, ti, mul2(cc2, ui));
            }
        }
    }
}

__device__ __forceinline__ void applyD2(ull (&vr)[8], ull (&vi)[8], int base, int j) {
    const float2* __restrict__ t = g_diag + j * 256 + base;
#pragma unroll
    for (int k = 0; k < 8; k++) {
        float2 p = __ldg(&t[k]);     // one load serves both samples
        ull px2  = pack2(p.x,  p.x);
        ull py2  = pack2(p.y,  p.y);
        ull pyn2 = pack2(-p.y, -p.y);
        ull nr = fma2(px2, vr[k], mul2(pyn2, vi[k]));
        ull ni = fma2(px2, vi[k], mul2(py2,  vr[k]));
        vr[k] = nr; vi[k] = ni;
    }
}

__global__ void __launch_bounds__(128)
qsim(const float* __restrict__ x, float* __restrict__ out, int W) {
    int warp = (blockIdx.x * blockDim.x + threadIdx.x) >> 5;  // 0..W-1
    int lane = threadIdx.x & 31;
    if (warp >= W) return;
    int base = lane * 8;

    // ---- encoding: lanes 0-15 carry the 16 angles of samples (2w, 2w+1) ----
    float xq = x[warp * 16 + (lane & 15)];
    float sh, ch;
    __sincosf(0.5f * xq, &sh, &ch);

    float c0[8], s0[8], c1[8], s1[8];
#pragma unroll
    for (int q = 0; q < 8; q++) {
        c0[q] = __shfl_sync(FULL, ch, q);
        s0[q] = __shfl_sync(FULL, sh, q);
        c1[q] = __shfl_sync(FULL, ch, 8 + q);
        s1[q] = __shfl_sync(FULL, sh, 8 + q);
    }
    float lp0 = 1.f, lp1 = 1.f;
#pragma unroll
    for (int q = 0; q < 5; q++) {
        bool b = (lane >> (4 - q)) & 1;
        lp0 *= b ? s0[q] : c0[q];
        lp1 *= b ? s1[q] : c1[q];
    }

    ull vr[8], vi[8];
#pragma unroll
    for (int k = 0; k < 8; k++) {
        float f0 = (((k >> 2) & 1) ? s0[5] : c0[5]) *
                   (((k >> 1) & 1) ? s0[6] : c0[6]) *
                   (((k)      & 1) ? s0[7] : c0[7]);
        float f1 = (((k >> 2) & 1) ? s1[5] : c1[5]) *
                   (((k >> 1) & 1) ? s1[6] : c1[6]) *
                   (((k)      & 1) ? s1[7] : c1[7]);
        float2 p0 = __ldg(&g_diag[base + k]);   // D0 table
        float amp0 = lp0 * f0, amp1 = lp1 * f1;
        vr[k] = pack2(amp0 * p0.x, amp1 * p0.x);
        vi[k] = pack2(amp0 * p0.y, amp1 * p0.y);
    }

    // ---- RyBlock layer 1 ----
    rygate2<0x80, 0x80,  0>(vr, vi, lane);
    rygate2<0x40, 0x40,  1>(vr, vi, lane);
    rygate2<0x20, 0x20,  2>(vr, vi, lane);
    rygate2<0x10, 0x10,  3>(vr, vi, lane);
    rygate2<0x08, 0x08,  4>(vr, vi, lane);
    rygate2<0x04, 0x04,  5>(vr, vi, lane);
    rygate2<0x02, 0x02,  6>(vr, vi, lane);
    rygate2<0x01, 0x01,  7>(vr, vi, lane);
    applyD2(vr, vi, base, 1);
    // ---- layer 2 ----
    rygate2<0xC0, 0x80,  8>(vr, vi, lane);
    rygate2<0x60, 0xC0,  9>(vr, vi, lane);
    rygate2<0x30, 0xE0, 10>(vr, vi, lane);
    rygate2<0x18, 0xF0, 11>(vr, vi, lane);
    rygate2<0x0C, 0xF8, 12>(vr, vi, lane);
    rygate2<0x06, 0xFC, 13>(vr, vi, lane);
    rygate2<0x03, 0xFE, 14>(vr, vi, lane);
    rygate2<0x01, 0xFF, 15>(vr, vi, lane);
    applyD2(vr, vi, base, 2);
    // ---- layer 3 ----
    rygate2<0xA0, 0x80, 16>(vr, vi, lane);
    rygate2<0x50, 0x40, 17>(vr, vi, lane);
    rygate2<0x28, 0xA0, 18>(vr, vi, lane);
    rygate2<0x14, 0x50, 19>(vr, vi, lane);
    rygate2<0x0A, 0xA8, 20>(vr, vi, lane);
    rygate2<0x05, 0x54, 21>(vr, vi, lane);
    rygate2<0x02, 0xAA, 22>(vr, vi, lane);
    rygate2<0x01, 0x55, 23>(vr, vi, lane);
    applyD2(vr, vi, base, 3);
    // ---- layer 4 (trailing diagonal dropped: |amp|^2 invariant) ----
    rygate2<0xF0, 0x80, 24>(vr, vi, lane);
    rygate2<0x78, 0xC0, 25>(vr, vi, lane);
    rygate2<0x3C, 0x60, 26>(vr, vi, lane);
    rygate2<0x1E, 0x30, 27>(vr, vi, lane);
    rygate2<0x0F, 0x98, 28>(vr, vi, lane);
    rygate2<0x07, 0xCC, 29>(vr, vi, lane);
    rygate2<0x03, 0x66, 30>(vr, vi, lane);
    rygate2<0x01, 0x33, 31>(vr, vi, lane);

    // ---- measurement (rows: 80,40,20,10,88,44,22,11) for both samples ----
    float P0 = 0.f, A2 = 0.f, A1 = 0.f, A0 = 0.f;
    float P1 = 0.f, B2 = 0.f, B1 = 0.f, B0 = 0.f;
#pragma unroll
    for (int k = 0; k < 8; k++) {
        float r0 = lo32(vr[k]), i0 = lo32(vi[k]);
        float r1 = hi32(vr[k]), i1 = hi32(vi[k]);
        float p0 = r0 * r0 + i0 * i0;
        float p1 = r1 * r1 + i1 * i1;
        P0 += p0;                        P1 += p1;
        A2 += (k & 4) ? -p0 : p0;        B2 += (k & 4) ? -p1 : p1;
        A1 += (k & 2) ? -p0 : p0;        B1 += (k & 2) ? -p1 : p1;
        A0 += (k & 1) ? -p0 : p0;        B0 += (k & 1) ? -p1 : p1;
    }
    float z[16];
    {
        float sg16 = (lane & 16) ? -1.f : 1.f;
        float sg8  = (lane & 8)  ? -1.f : 1.f;
        float sg4  = (lane & 4)  ? -1.f : 1.f;
        float sg2  = (lane & 2)  ? -1.f : 1.f;
        float sg11 = (__popc(lane & 0x11) & 1) ? -1.f : 1.f;
        z[0] = sg16 * P0;  z[1] = sg8 * P0;  z[2] = sg4 * P0;  z[3] = sg2 * P0;
        z[4] = sg11 * P0;  z[5] = sg8 * A2;  z[6] = sg4 * A1;  z[7] = sg2 * A0;
        z[8]  = sg16 * P1; z[9]  = sg8 * P1; z[10] = sg4 * P1; z[11] = sg2 * P1;
        z[12] = sg11 * P1; z[13] = sg8 * B2; z[14] = sg4 * B1; z[15] = sg2 * B0;
    }
#pragma unroll
    for (int off = 16; off >= 1; off >>= 1) {
#pragma unroll
        for (int i = 0; i < 16; i++)
            z[i] += __shfl_xor_sync(FULL, z[i], off);
    }
    if (lane == 0) {
        float4* o = (float4*)(out + warp * 16);
        o[0] = make_float4(z[0],  z[1],  z[2],  z[3]);
        o[1] = make_float4(z[4],  z[5],  z[6],  z[7]);
        o[2] = make_float4(z[8],  z[9],  z[10], z[11]);
        o[3] = make_float4(z[12], z[13], z[14], z[15]);
    }
}

extern "C" void kernel_launch(void* const* d_in, const int* in_sizes, int n_in,
                              void* d_out, int out_size) {
    const float* x = (const float*)d_in[0];
    const float* w = (const float*)d_in[1];
    float* out = (float*)d_out;
    int B = in_sizes[0] / 8;
    int W = B / 2;   // 2 samples per warp, packed into f32x2 lanes

    prep<<<1, 1024>>>(w);

    int threads = 128;
    long long total = (long long)W * 32;
    int blocks = (int)((total + threads - 1) / threads);
    qsim<<<blocks, threads>>>(x, out, W);
}

// round 9
// speedup vs baseline: 1.3219x; 1.0600x over previous
#include <cuda_runtime.h>
#include <cuda_bf16.h>

#define FULL 0xFFFFFFFFu
typedef unsigned long long ull;

// Per-gate Ry part: (cos(theta/2), sin(theta/2)) from ZYZ decomposition
__device__ float2 g_ry[32];
// Diagonal phase tables D0..D3: 4 x 256 complex (cos, sin)
__device__ float2 g_diag[4 * 256];

// Relabeled parity rows per gate (CNOTs folded; must match template R args)
__constant__ int c_rows[32] = {
    0x80,0x40,0x20,0x10,0x08,0x04,0x02,0x01,
    0x80,0xC0,0xE0,0xF0,0xF8,0xFC,0xFE,0xFF,
    0x80,0x40,0xA0,0x50,0xA8,0x54,0xAA,0x55,
    0x80,0xC0,0x60,0x30,0x98,0xCC,0x66,0x33
};

// ---- single fused prep kernel (1024 threads, one block) ----
__global__ void prep(const float* __restrict__ w) {
    __shared__ float s_lam[32], s_phi[32];
    int t = threadIdx.x;
    if (t < 32) {
        int base = t * 3;
        float ta = w[base]     * 0.5f;
        float tb = w[base + 1] * 0.5f;
        float tc = w[base + 2] * 0.5f;
        float sa = sinf(ta), ca = cosf(ta);
        float sb = sinf(tb), cb = cosf(tb);
        float sc = sinf(tc), cc = cosf(tc);
        float m00r = cb * ca, m00i = sb * sa;
        float m01r = -sb * ca, m01i = -cb * sa;
        float x = cc * m00r + sc * m00i;
        float y = cc * m00i - sc * m00r;
        float z = cc * m01r + sc * m01i;
        float q = cc * m01i - sc * m01r;
        float ct = sqrtf(x * x + y * y);
        float st = sqrtf(z * z + q * q);
        float a = -atan2f(y, x);
        float b = atan2f(q, -z);
        g_ry[t] = make_float2(ct, st);
        s_lam[t] = a - b;
        s_phi[t] = a + b;
    }
    __syncthreads();

    int j = t >> 8;
    int s = t & 255;
    float th = 0.f;
#pragma unroll
    for (int g = 0; g < 8; g++) {
        int gg = 8 * j + g;
        float sg = (__popc(c_rows[gg] & s) & 1) ? 1.f : -1.f;
        th += 0.5f * s_lam[gg] * sg;
    }
    if (j > 0) {
#pragma unroll
        for (int g = 0; g < 8; g++) {
            int gg = 8 * (j - 1) + g;
            float sg = (__popc(c_rows[gg] & s) & 1) ? 1.f : -1.f;
            th += 0.5f * s_phi[gg] * sg;
        }
    }
    float sn, cn;
    __sincosf(th, &sn, &cn);
    g_diag[j * 256 + s] = make_float2(cn, sn);
}

// ---- packed fp32x2 helpers: lanes = (sampleA, sampleB) ----
__device__ __forceinline__ ull fma2(ull a, ull b, ull c) {
    ull d; asm("fma.rn.f32x2 %0, %1, %2, %3;" : "=l"(d) : "l"(a), "l"(b), "l"(c));
    return d;
}
__device__ __forceinline__ ull mul2(ull a, ull b) {
    ull d; asm("mul.rn.f32x2 %0, %1, %2;" : "=l"(d) : "l"(a), "l"(b));
    return d;
}
__device__ __forceinline__ ull pack2(float lo, float hi) {
    ull d; asm("mov.b64 %0, {%1, %2};" : "=l"(d) : "f"(lo), "f"(hi));
    return d;
}
__device__ __forceinline__ float lo32(ull v) { return __uint_as_float((unsigned)v); }
__device__ __forceinline__ float hi32(ull v) { return __uint_as_float((unsigned)(v >> 32)); }

// ---- Ry gate, 16-lane layout: lane4 bits = state bits 7..4, k = bits 3..0
// new[s] = c*a[s] + sigma(s)*st*a[s^M], sigma = +1 if <R,s> odd else -1.
// 0x6996 = parity lookup for 4-bit values.
template<int M, int R, int G>
__device__ __forceinline__ void rygate(ull (&vr)[16], ull (&vi)[16], int lane4) {
    const float2 cs = g_ry[G];
    constexpr int ML = (M >> 4) & 15;
    constexpr int MK = M & 15;
    constexpr int RL = (R >> 4) & 15;
    constexpr int RK = R & 15;
    constexpr int HB = (MK >= 8) ? 8 : (MK >= 4) ? 4 : (MK >= 2) ? 2 : 1;

    int pl = (0x6996 >> (lane4 & RL)) & 1;
    float sA = pl ? cs.y : -cs.y;
    ull cc2 = pack2(cs.x, cs.x);
    ull sP  = pack2(sA, sA);
    ull sN  = pack2(-sA, -sA);

    if constexpr (ML != 0 && MK == 0) {
        // cross-lane, same local slot: lockstep shuffle reads old value, safe
#pragma unroll
        for (int k = 0; k < 16; k++) {
            ull br = __shfl_xor_sync(FULL, vr[k], ML);
            ull bi = __shfl_xor_sync(FULL, vi[k], ML);
            ull sk = ((0x6996 >> (RK & k)) & 1) ? sN : sP;  // compile-time select
            vr[k] = fma2(sk, br, mul2(cc2, vr[k]));
            vi[k] = fma2(sk, bi, mul2(cc2, vi[k]));
        }
    } else if constexpr (ML != 0) {
        // mixed: pair-complete — all shuffles of pair (k, k^MK) before any write
#pragma unroll
        for (int k = 0; k < 16; k++) {
            if ((k & HB) == 0) {
                const int k2 = k ^ MK;
                ull pr = __shfl_xor_sync(FULL, vr[k2], ML);
                ull pi = __shfl_xor_sync(FULL, vi[k2], ML);
                ull qr = __shfl_xor_sync(FULL, vr[k],  ML);
                ull qi = __shfl_xor_sync(FULL, vi[k],  ML);
                ull s1 = ((0x6996 >> (RK & k )) & 1) ? sN : sP;
                ull s2 = ((0x6996 >> (RK & k2)) & 1) ? sN : sP;
                vr[k]  = fma2(s1, pr, mul2(cc2, vr[k]));
                vi[k]  = fma2(s1, pi, mul2(cc2, vi[k]));
                vr[k2] = fma2(s2, qr, mul2(cc2, vr[k2]));
                vi[k2] = fma2(s2, qi, mul2(cc2, vi[k2]));
            }
        }
    } else {
        // purely local pairs, in place
#pragma unroll
        for (int k = 0; k < 16; k++) {
            if ((k & HB) == 0) {
                const int k2 = k ^ MK;
                ull s1 = ((0x6996 >> (RK & k )) & 1) ? sN : sP;
                ull s2 = ((0x6996 >> (RK & k2)) & 1) ? sN : sP;
                ull tr = vr[k], ti = vi[k], ur = vr[k2], ui = vi[k2];
                vr[k]  = fma2(s1, ur, mul2(cc2, tr));
                vi[k]  = fma2(s1, ui, mul2(cc2, ti));
                vr[k2] = fma2(s2, tr, mul2(cc2, ur));
                vi[k2] = fma2(s2, ti, mul2(cc2, ui));
            }
        }
    }
}

__device__ __forceinline__ void applyD(ull (&vr)[16], ull (&vi)[16], int lane4, int j) {
    const float4* __restrict__ t = (const float4*)(g_diag + j * 256 + lane4 * 16);
#pragma unroll
    for (int h = 0; h < 8; h++) {
        float4 p = __ldg(&t[h]);    // two slots' phases; serves both samples
        int k = 2 * h;
        {
            ull px = pack2(p.x, p.x), py = pack2(p.y, p.y), pyn = pack2(-p.y, -p.y);
            ull nr = fma2(px, vr[k], mul2(pyn, vi[k]));
            ull ni = fma2(px, vi[k], mul2(py,  vr[k]));
            vr[k] = nr; vi[k] = ni;
        }
        {
            ull px = pack2(p.z, p.z), py = pack2(p.w, p.w), pyn = pack2(-p.w, -p.w);
            ull nr = fma2(px, vr[k+1], mul2(pyn, vi[k+1]));
            ull ni = fma2(px, vi[k+1], mul2(py,  vr[k+1]));
            vr[k+1] = nr; vi[k+1] = ni;
        }
    }
}

__global__ void __launch_bounds__(128)
qsim(const float* __restrict__ x, float* __restrict__ out, int W) {
    int warp = (blockIdx.x * blockDim.x + threadIdx.x) >> 5;  // 0..W-1
    int lane = threadIdx.x & 31;
    if (warp >= W) return;
    int lane4 = lane & 15;    // state bits 7..4 (qubits 0..3)
    int grp = lane >> 4;      // half-warp group: samples (4w+2g, 4w+2g+1)

    // ---- encoding: 32 lanes load the 32 angles of 4 samples ----
    float xq = x[warp * 32 + lane];
    float sh, ch;
    __sincosf(0.5f * xq, &sh, &ch);

    // group g's samples: angles at lanes 16g+q (sample A) and 16g+8+q (sample B)
    float c0[8], s0[8], c1[8], s1[8];
#pragma unroll
    for (int q = 0; q < 8; q++) {
        c0[q] = __shfl_sync(FULL, ch, (lane & 16) + q);
        s0[q] = __shfl_sync(FULL, sh, (lane & 16) + q);
        c1[q] = __shfl_sync(FULL, ch, (lane & 16) + 8 + q);
        s1[q] = __shfl_sync(FULL, sh, (lane & 16) + 8 + q);
    }
    // lane4 bit(3-q) selects qubit q=0..3
    float lp0 = ((lane4 & 8) ? s0[0] : c0[0]) * ((lane4 & 4) ? s0[1] : c0[1]) *
                ((lane4 & 2) ? s0[2] : c0[2]) * ((lane4 & 1) ? s0[3] : c0[3]);
    float lp1 = ((lane4 & 8) ? s1[0] : c1[0]) * ((lane4 & 4) ? s1[1] : c1[1]) *
                ((lane4 & 2) ? s1[2] : c1[2]) * ((lane4 & 1) ? s1[3] : c1[3]);

    // e[j]: product over qubits 5..7 (k bits 2..0), lp folded in
    float e0[8], e1[8];
#pragma unroll
    for (int j2 = 0; j2 < 8; j2++) {
        e0[j2] = lp0 * ((j2 & 4) ? s0[5] : c0[5]) * ((j2 & 2) ? s0[6] : c0[6]) *
                       ((j2 & 1) ? s0[7] : c0[7]);
        e1[j2] = lp1 * ((j2 & 4) ? s1[5] : c1[5]) * ((j2 & 2) ? s1[6] : c1[6]) *
                       ((j2 & 1) ? s1[7] : c1[7]);
    }

    // init: amp product (qubit4 factor inline) folded with D0 phase
    ull vr[16], vi[16];
    {
        const float4* __restrict__ d0p = (const float4*)(g_diag + lane4 * 16);
#pragma unroll
        for (int h = 0; h < 8; h++) {
            float4 p = __ldg(&d0p[h]);
            int k = 2 * h;
            float a0 = ((k & 8) ? s0[4] : c0[4]) * e0[k & 7];
            float a1 = ((k & 8) ? s1[4] : c1[4]) * e1[k & 7];
            vr[k] = pack2(a0 * p.x, a1 * p.x);
            vi[k] = pack2(a0 * p.y, a1 * p.y);
            int k2 = k + 1;
            float b0 = ((k2 & 8) ? s0[4] : c0[4]) * e0[k2 & 7];
            float b1 = ((k2 & 8) ? s1[4] : c1[4]) * e1[k2 & 7];
            vr[k2] = pack2(b0 * p.z, b1 * p.z);
            vi[k2] = pack2(b0 * p.w, b1 * p.w);
        }
    }

    // ---- RyBlock layer 1 ----
    rygate<0x80, 0x80,  0>(vr, vi, lane4);
    rygate<0x40, 0x40,  1>(vr, vi, lane4);
    rygate<0x20, 0x20,  2>(vr, vi, lane4);
    rygate<0x10, 0x10,  3>(vr, vi, lane4);
    rygate<0x08, 0x08,  4>(vr, vi, lane4);
    rygate<0x04, 0x04,  5>(vr, vi, lane4);
    rygate<0x02, 0x02,  6>(vr, vi, lane4);
    rygate<0x01, 0x01,  7>(vr, vi, lane4);
    applyD(vr, vi, lane4, 1);
    // ---- layer 2 ----
    rygate<0xC0, 0x80,  8>(vr, vi, lane4);
    rygate<0x60, 0xC0,  9>(vr, vi, lane4);
    rygate<0x30, 0xE0, 10>(vr, vi, lane4);
    rygate<0x18, 0xF0, 11>(vr, vi, lane4);
    rygate<0x0C, 0xF8, 12>(vr, vi, lane4);
    rygate<0x06, 0xFC, 13>(vr, vi, lane4);
    rygate<0x03, 0xFE, 14>(vr, vi, lane4);
    rygate<0x01, 0xFF, 15>(vr, vi, lane4);
    applyD(vr, vi, lane4, 2);
    // ---- layer 3 ----
    rygate<0xA0, 0x80, 16>(vr, vi, lane4);
    rygate<0x50, 0x40, 17>(vr, vi, lane4);
    rygate<0x28, 0xA0, 18>(vr, vi, lane4);
    rygate<0x14, 0x50, 19>(vr, vi, lane4);
    rygate<0x0A, 0xA8, 20>(vr, vi, lane4);
    rygate<0x05, 0x54, 21>(vr, vi, lane4);
    rygate<0x02, 0xAA, 22>(vr, vi, lane4);
    rygate<0x01, 0x55, 23>(vr, vi, lane4);
    applyD(vr, vi, lane4, 3);
    // ---- layer 4 (trailing diagonal dropped: |amp|^2 invariant) ----
    rygate<0xF0, 0x80, 24>(vr, vi, lane4);
    rygate<0x78, 0xC0, 25>(vr, vi, lane4);
    rygate<0x3C, 0x60, 26>(vr, vi, lane4);
    rygate<0x1E, 0x30, 27>(vr, vi, lane4);
    rygate<0x0F, 0x98, 28>(vr, vi, lane4);
    rygate<0x07, 0xCC, 29>(vr, vi, lane4);
    rygate<0x03, 0x66, 30>(vr, vi, lane4);
    rygate<0x01, 0x33, 31>(vr, vi, lane4);

    // ---- measurement: rows q0..q7 = 80,40,20,10,88,44,22,11 ----
    float P0 = 0.f, S80 = 0.f, S40 = 0.f, S20 = 0.f, S10 = 0.f;
    float P1 = 0.f, S81 = 0.f, S41 = 0.f, S21 = 0.f, S11 = 0.f;
#pragma unroll
    for (int k = 0; k < 16; k++) {
        float r0 = lo32(vr[k]), i0 = lo32(vi[k]);
        float r1 = hi32(vr[k]), i1 = hi32(vi[k]);
        float p0 = r0 * r0 + i0 * i0;
        float p1 = r1 * r1 + i1 * i1;
        P0 += p0;                          P1 += p1;
        S80 += (k & 8) ? -p0 : p0;         S81 += (k & 8) ? -p1 : p1;
        S40 += (k & 4) ? -p0 : p0;         S41 += (k & 4) ? -p1 : p1;
        S20 += (k & 2) ? -p0 : p0;         S21 += (k & 2) ? -p1 : p1;
        S10 += (k & 1) ? -p0 : p0;         S11 += (k & 1) ? -p1 : p1;
    }
    float g8 = (lane4 & 8) ? -1.f : 1.f;
    float g4 = (lane4 & 4) ? -1.f : 1.f;
    float g2 = (lane4 & 2) ? -1.f : 1.f;
    float g1 = (lane4 & 1) ? -1.f : 1.f;
    float z[16];
    z[0]  = g8 * P0;   z[1]  = g4 * P0;   z[2]  = g2 * P0;   z[3]  = g1 * P0;
    z[4]  = g8 * S80;  z[5]  = g4 * S40;  z[6]  = g2 * S20;  z[7]  = g1 * S10;
    z[8]  = g8 * P1;   z[9]  = g4 * P1;   z[10] = g2 * P1;   z[11] = g1 * P1;
    z[12] = g8 * S81;  z[13] = g4 * S41;  z[14] = g2 * S21;  z[15] = g1 * S11;

#pragma unroll
    for (int off = 8; off >= 1; off >>= 1) {
#pragma unroll
        for (int i = 0; i < 16; i++)
            z[i] += __shfl_xor_sync(FULL, z[i], off);
    }
    if (lane4 == 0) {
        float4* o = (float4*)(out + warp * 32 + grp * 16);
        o[0] = make_float4(z[0],  z[1],  z[2],  z[3]);
        o[1] = make_float4(z[4],  z[5],  z[6],  z[7]);
        o[2] = make_float4(z[8],  z[9],  z[10], z[11]);
        o[3] = make_float4(z[12], z[13], z[14], z[15]);
    }
}

extern "C" void kernel_launch(void* const* d_in, const int* in_sizes, int n_in,
                              void* d_out, int out_size) {
    const float* x = (const float*)d_in[0];
    const float* w = (const float*)d_in[1];
    float* out = (float*)d_out;
    int B = in_sizes[0] / 8;
    int W = B / 4;   // 4 samples per warp (16-lane groups, f32x2-packed pairs)

    prep<<<1, 1024>>>(w);

    int threads = 128;
    long long total = (long long)W * 32;
    int blocks = (int)((total + threads - 1) / threads);
    qsim<<<blocks, threads>>>(x, out, W);
}